// round 14
// baseline (speedup 1.0000x reference)
#include <cuda_runtime.h>
#include <cstdint>

#define T_STEPS   4096
#define HID       2048
#define IN_DIM    128
#define NCTA      128
#define ROWS_CTA  16
#define NTHREADS  1024
#define LEAK      0.9f
#define TT        64      // prologue time-tile

typedef unsigned long long u64;

// Persistent cross-replay state. Tags are MONOTONIC mod 256 (base advances by
// T_STEPS per launch). Lockstep skew <= 1 step => live tags differ from the
// expected one by {0, +-2} mod 256 — exact-match is unambiguous.
__device__ unsigned g_tag32[2][HID];        // (tag8<<24) | (fp32 act rounded to top 24 bits)
__device__ int      g_base[NCTA][32];       // per-CTA base counter, 128B sector each
__device__ float    g_ip[T_STEPS * HID];    // precomputed input projection (32 MB, static)

__device__ __forceinline__ unsigned ld_relaxed32(const unsigned* p) {
    unsigned v;
    asm volatile("ld.relaxed.gpu.global.b32 %0, [%1];" : "=r"(v) : "l"(p));
    return v;
}
__device__ __forceinline__ void st_relaxed32(unsigned* p, unsigned v) {
    asm volatile("st.relaxed.gpu.global.b32 [%0], %1;" :: "l"(p), "r"(v));
}
// tanh(x) = sign(x) * (1 - 2/(exp(2|x|)+1)); MUFU-based.
__device__ __forceinline__ float fast_tanh(float x) {
    float e = __expf(2.0f * fabsf(x));
    float r = 1.0f - __fdividef(2.0f, e + 1.0f);
    return copysignf(r, x);
}

__global__ void __launch_bounds__(NTHREADS, 1)
reservoir_kernel(const float* __restrict__ input,   // [T, IN_DIM]
                 const float* __restrict__ w_ih,    // [HID, IN_DIM]
                 const float* __restrict__ b_ih,    // [HID]
                 const float* __restrict__ w_hh,    // [HID, HID]
                 float* __restrict__ out)           // [2, T, HID] (act, hid)
{
    // pool: prologue input tile overlays main-loop red_s (barrier-gated epochs)
    __shared__ __align__(16) float shpool[TT * 132];          // 33792 B
    __shared__ __align__(16) float w_ih_s[ROWS_CTA][132];
    __shared__ float hid_s[ROWS_CTA];
    __shared__ float b_s[ROWS_CTA];
    __shared__ int   base_s;

    float (*red_s)[ROWS_CTA][16] = (float(*)[ROWS_CTA][16])shpool;  // [2][16][16] parity
    float (*tile)[132]           = (float(*)[132])shpool;           // prologue overlay

    const int tid  = threadIdx.x;
    const int cta  = blockIdx.x;
    const int r0   = cta * ROWS_CTA;
    const int half = tid >> 9;       // 0: local rows 0..7, 1: rows 8..15
    const int slot = tid & 511;      // cols [4*slot, 4*slot+4)
    const int warp = tid >> 5;
    const int lane = tid & 31;

    // ---- one-time setup ----
    {
        const float4* w4p = (const float4*)(w_ih + r0 * IN_DIM);
        for (int i = tid; i < ROWS_CTA * (IN_DIM / 4); i += NTHREADS) {
            int row = i >> 5, c = i & 31;
            *(float4*)&w_ih_s[row][4 * c] = w4p[i];
        }
    }
    if (tid < ROWS_CTA) { b_s[tid] = b_ih[r0 + tid]; hid_s[tid] = 0.0f; }
    if (tid == 0) base_s = g_base[cta][0];

    // w_hh rows for this CTA -> registers (128 KB/CTA)
    float4 w4[8];
    {
        const float4* w_hh4 = (const float4*)w_hh;
        const int rbase = r0 + half * 8;
        #pragma unroll
        for (int i = 0; i < 8; i++)
            w4[i] = w_hh4[(size_t)(rbase + i) * (HID / 4) + slot];
    }

    // ---- PROLOGUE: inp_proj for this CTA's 16 rows, all T steps -> g_ip ----
    {
        const int trow = tid >> 4;          // 0..63
        const int row  = tid & 15;
        for (int t0 = 0; t0 < T_STEPS; t0 += TT) {
            __syncthreads();
            const float4* in4 = (const float4*)(input + t0 * IN_DIM);
            for (int i = tid; i < TT * (IN_DIM / 4); i += NTHREADS) {
                int tt = i >> 5, c = i & 31;
                *(float4*)&tile[tt][4 * c] = in4[i];
            }
            __syncthreads();
            float acc = 0.0f;
            #pragma unroll
            for (int j = 0; j < 32; j++) {
                float4 uv = *(const float4*)&tile[trow][4 * j];
                float4 wv = *(const float4*)&w_ih_s[row][4 * j];
                acc = fmaf(uv.x, wv.x, fmaf(uv.y, wv.y,
                      fmaf(uv.z, wv.z, fmaf(uv.w, wv.w, acc))));
            }
            g_ip[(size_t)(t0 + trow) * HID + r0 + row] = acc + b_s[row];
        }
    }
    __syncthreads();    // prologue done; tile overlay free for red_s
    const int base = base_s;

    float* __restrict__ out_act = out;
    float* __restrict__ out_hid = out + (size_t)T_STEPS * HID;

    // ip register pipeline for Phase C threads (consume t, hold t+1, fetch t+2)
    float ipc = 0.0f, ipn = 0.0f;
    if (tid < ROWS_CTA) {
        ipc = __ldcg(&g_ip[(size_t)0 * HID + r0 + tid]);
        ipn = __ldcg(&g_ip[(size_t)1 * HID + r0 + tid]);
    }

    for (int t = 0; t < T_STEPS; t++) {
        // ---- DIRECT poll: each thread waits on exactly the 4 packed words it
        // consumes (16 contiguous bytes; warp footprint = its own 4 sectors).
        // No bar A, no smem rebroadcast: each warp starts FMA+fold the moment
        // its sectors land, overlapping other warps' detection. Redundancy is
        // 2x (halves share sectors) -> 16 KB/CTA/round, in the weakly-paced
        // range per R12. Tag8 exact-match unambiguous (<=1-step skew).
        float4 a4;
        if (t > 0) {
            const unsigned te = ((unsigned)(base + t) & 0xFFu) << 24;
            const unsigned* src = &g_tag32[(t - 1) & 1][4 * slot];
            unsigned w0, w1, w2, w3;
            for (;;) {
                w0 = ld_relaxed32(src + 0);
                w1 = ld_relaxed32(src + 1);
                w2 = ld_relaxed32(src + 2);
                w3 = ld_relaxed32(src + 3);
                if ((((w0 ^ te) | (w1 ^ te) | (w2 ^ te) | (w3 ^ te)) >> 24) == 0u)
                    break;
            }
            a4.x = __uint_as_float(w0 << 8);   // restore sign+exp+mant15
            a4.y = __uint_as_float(w1 << 8);
            a4.z = __uint_as_float(w2 << 8);
            a4.w = __uint_as_float(w3 << 8);
        } else {
            a4 = make_float4(0.f, 0.f, 0.f, 0.f);
        }

        // ---- Phase B: recurrent matvec on register weights (champion fold) ----
        float v[8];
        #pragma unroll
        for (int i = 0; i < 8; i++)
            v[i] = fmaf(w4[i].x, a4.x,
                   fmaf(w4[i].y, a4.y,
                   fmaf(w4[i].z, a4.z, w4[i].w * a4.w)));

        // select-then-shuffle fold: 8 accumulators -> row sums in lanes 0..7
        #pragma unroll
        for (int k = 0; k < 4; k++) {
            float give = (lane & 1) ? v[2 * k] : v[2 * k + 1];
            float got  = __shfl_xor_sync(0xFFFFFFFFu, give, 1);
            v[k] = ((lane & 1) ? v[2 * k + 1] : v[2 * k]) + got;
        }
        #pragma unroll
        for (int k = 0; k < 2; k++) {
            float give = (lane & 2) ? v[2 * k] : v[2 * k + 1];
            float got  = __shfl_xor_sync(0xFFFFFFFFu, give, 2);
            v[k] = ((lane & 2) ? v[2 * k + 1] : v[2 * k]) + got;
        }
        float s;
        {
            float give = (lane & 4) ? v[0] : v[1];
            float got  = __shfl_xor_sync(0xFFFFFFFFu, give, 4);
            s = ((lane & 4) ? v[1] : v[0]) + got;
        }
        s += __shfl_xor_sync(0xFFFFFFFFu, s, 8);
        s += __shfl_xor_sync(0xFFFFFFFFu, s, 16);
        if (lane < 8) red_s[t & 1][half * 8 + lane][warp & 15] = s;
        __syncthreads();                                 // bar B (only barrier/step)

        // ---- Phase C: final reduce + nonlinearity + publish (threads 0..15) ----
        if (tid < ROWS_CTA) {
            const int row = tid;
            float4 s0 = *(const float4*)&red_s[t & 1][row][0];
            float4 s1 = *(const float4*)&red_s[t & 1][row][4];
            float4 s2 = *(const float4*)&red_s[t & 1][row][8];
            float4 s3 = *(const float4*)&red_s[t & 1][row][12];
            float sx = ((s0.x + s1.x) + (s2.x + s3.x)) + ((s0.y + s1.y) + (s2.y + s3.y));
            float sy = ((s0.z + s1.z) + (s2.z + s3.z)) + ((s0.w + s1.w) + (s2.w + s3.w));
            float tot = sx + sy;

            const float nh = (1.0f - LEAK) * hid_s[row] + LEAK * (ipc + tot);
            const float na = fast_tanh(nh);
            hid_s[row] = nh;

            const int gr = r0 + row;
            // round fp32 to top-24 bits (nearest), pack with 8-bit tag
            unsigned bits = __float_as_uint(na);
            unsigned pk = ((bits + 0x80u) >> 8) & 0x00FFFFFFu;
            pk |= ((unsigned)(base + t + 1) & 0xFFu) << 24;
            st_relaxed32(&g_tag32[t & 1][gr], pk);       // one 64B coalesced publish

            out_act[(size_t)t * HID + gr] = na;
            out_hid[(size_t)t * HID + gr] = nh;

            // advance ip pipeline (slack: consumed 2 steps from issue)
            ipc = ipn;
            int tn = (t + 2 < T_STEPS) ? t + 2 : T_STEPS - 1;
            ipn = __ldcg(&g_ip[(size_t)tn * HID + gr]);
        }
        // No trailing barrier. red_s parity slot (t&1) is rewritten at t+2,
        // after the writer's detect(t+2) <= all CTAs' publish(t+1) <= this
        // CTA's barB(t+1) <= Phase C(t) reads complete. g_tag32 slot overwrite
        // (tag t+3, step t+2) requires producer detect(t+2) <= all publishes
        // (t+1) <= every consumer's tag-(t+1) poll done — nobody is lapped;
        // concurrent writers differ by +-2 mod 256, never a false match.
    }

    if (tid == 0) g_base[cta][0] = base + T_STEPS;   // advance tags for next replay
}

extern "C" void kernel_launch(void* const* d_in, const int* in_sizes, int n_in,
                              void* d_out, int out_size) {
    const float* input = (const float*)d_in[0];   // [4096, 128]
    const float* w_ih  = (const float*)d_in[1];   // [2048, 128]
    const float* b_ih  = (const float*)d_in[2];   // [2048]
    const float* w_hh  = (const float*)d_in[3];   // [2048, 2048]
    float* out = (float*)d_out;                   // [2, 4096, 2048]

    reservoir_kernel<<<NCTA, NTHREADS>>>(input, w_ih, b_ih, w_hh, out);
}

// round 15
// speedup vs baseline: 2.7209x; 2.7209x over previous
#include <cuda_runtime.h>
#include <cstdint>

#define T_STEPS   4096
#define HID       2048
#define IN_DIM    128
#define NCTA      128
#define ROWS_CTA  16
#define NTHREADS  1024
#define LEAK      0.9f
#define TT        64      // prologue time-tile

typedef unsigned long long u64;

// Persistent cross-replay state. Tags are MONOTONIC mod 256 (base advances by
// T_STEPS per launch). Lockstep skew <= 1 step => live tags differ from the
// expected one by {0, +-2} mod 256 — exact-match is unambiguous.
__device__ unsigned g_tag32[2][HID];        // (tag8<<24) | (fp32 act rounded to top 24 bits)
__device__ int      g_base[NCTA][32];       // per-CTA base counter, 128B sector each
__device__ float    g_ip[T_STEPS * HID];    // precomputed input projection (32 MB, static)

__device__ __forceinline__ unsigned ld_relaxed32(const unsigned* p) {
    unsigned v;
    asm volatile("ld.relaxed.gpu.global.b32 %0, [%1];" : "=r"(v) : "l"(p));
    return v;
}
__device__ __forceinline__ void st_relaxed32(unsigned* p, unsigned v) {
    asm volatile("st.relaxed.gpu.global.b32 [%0], %1;" :: "l"(p), "r"(v));
}
// tanh(x) = sign(x) * (1 - 2/(exp(2|x|)+1)); MUFU-based.
__device__ __forceinline__ float fast_tanh(float x) {
    float e = __expf(2.0f * fabsf(x));
    float r = 1.0f - __fdividef(2.0f, e + 1.0f);
    return copysignf(r, x);
}

__global__ void __launch_bounds__(NTHREADS, 1)
reservoir_kernel(const float* __restrict__ input,   // [T, IN_DIM]
                 const float* __restrict__ w_ih,    // [HID, IN_DIM]
                 const float* __restrict__ b_ih,    // [HID]
                 const float* __restrict__ w_hh,    // [HID, HID]
                 float* __restrict__ out)           // [2, T, HID] (act, hid)
{
    // 33 KB pool: prologue overlays the input tile on top of main-loop a_sf/red_s
    __shared__ __align__(16) float shpool[TT * 132];          // 33792 B
    __shared__ __align__(16) float w_ih_s[ROWS_CTA][132];     // padded rows
    __shared__ float hid_s[ROWS_CTA];
    __shared__ float b_s[ROWS_CTA];
    __shared__ int   base_s;

    float*        a_sf  = shpool;                              // [2048] act broadcast
    float (*red_s)[16]  = (float(*)[16])(shpool + 2048);       // [16][16]
    float (*tile)[132]  = (float(*)[132])shpool;               // prologue overlay

    const int tid  = threadIdx.x;
    const int cta  = blockIdx.x;
    const int r0   = cta * ROWS_CTA;
    const int half = tid >> 9;       // 0: local rows 0..7, 1: rows 8..15
    const int slot = tid & 511;      // cols [4*slot, 4*slot+4)
    const int warp = tid >> 5;
    const int lane = tid & 31;

    // ---- one-time setup ----
    {
        const float4* w4p = (const float4*)(w_ih + r0 * IN_DIM);
        for (int i = tid; i < ROWS_CTA * (IN_DIM / 4); i += NTHREADS) {
            int row = i >> 5, c = i & 31;
            *(float4*)&w_ih_s[row][4 * c] = w4p[i];
        }
    }
    if (tid < ROWS_CTA) { b_s[tid] = b_ih[r0 + tid]; hid_s[tid] = 0.0f; }
    if (tid == 0) base_s = g_base[cta][0];

    // w_hh rows for this CTA -> registers (128 KB/CTA)
    float4 w4[8];
    {
        const float4* w_hh4 = (const float4*)w_hh;
        const int rbase = r0 + half * 8;
        #pragma unroll
        for (int i = 0; i < 8; i++)
            w4[i] = w_hh4[(size_t)(rbase + i) * (HID / 4) + slot];
    }

    // ---- PROLOGUE: inp_proj for this CTA's 16 rows, all T steps -> g_ip ----
    {
        const int trow = tid >> 4;          // 0..63
        const int row  = tid & 15;
        for (int t0 = 0; t0 < T_STEPS; t0 += TT) {
            __syncthreads();
            const float4* in4 = (const float4*)(input + t0 * IN_DIM);
            for (int i = tid; i < TT * (IN_DIM / 4); i += NTHREADS) {
                int tt = i >> 5, c = i & 31;
                *(float4*)&tile[tt][4 * c] = in4[i];
            }
            __syncthreads();
            float acc = 0.0f;
            #pragma unroll
            for (int j = 0; j < 32; j++) {
                float4 uv = *(const float4*)&tile[trow][4 * j];
                float4 wv = *(const float4*)&w_ih_s[row][4 * j];
                acc = fmaf(uv.x, wv.x, fmaf(uv.y, wv.y,
                      fmaf(uv.z, wv.z, fmaf(uv.w, wv.w, acc))));
            }
            g_ip[(size_t)(t0 + trow) * HID + r0 + row] = acc + b_s[row];
        }
    }
    __syncthreads();    // g_ip slice visible; tile overlay free for a_sf
    const int base = base_s;

    float* __restrict__ out_act = out;
    float* __restrict__ out_hid = out + (size_t)T_STEPS * HID;

    // ip register pipeline for Phase C threads (consume t, hold t+1, fetch t+2)
    float ipc = 0.0f, ipn = 0.0f;
    if (tid < ROWS_CTA) {
        ipc = __ldcg(&g_ip[(size_t)0 * HID + r0 + tid]);
        ipn = __ldcg(&g_ip[(size_t)1 * HID + r0 + tid]);
    }

    for (int t = 0; t < T_STEPS; t++) {
        // ---- Poll step t-1 with TWO phase-offset chains per thread.
        // Chain B is primed ~160 cyc after A via a dependent-IMAD delay chain
        // (feeds B's address so it cannot be elided). In the loop, each chain
        // re-issues right after ITS check, so the return->reissue coupling
        // preserves the offset: L2 sample period drops RT -> ~RT/2, cutting
        // the chip-wide E[max over 128 CTAs of phase quantization] (~RT) in
        // half. Footprint: 1 sector per LDG (contiguous {tid, tid+1024} map).
        if (t > 0) {
            const unsigned exp8 = (unsigned)(base + t) & 0xFFu;
            const unsigned* srcb = &g_tag32[(t - 1) & 1][0];
            unsigned a0 = ld_relaxed32(srcb + tid);
            unsigned a1 = ld_relaxed32(srcb + tid + 1024);
            unsigned d = (unsigned)tid | 1u;
            #pragma unroll
            for (int i = 0; i < 40; i++) d = d * 2654435761u + 1u;  // ~160 cyc dependent chain
            const unsigned* srcb2 = srcb + (d >> 31 >> 1);          // == srcb, chain-dependent
            unsigned b0 = ld_relaxed32(srcb2 + tid);
            unsigned b1 = ld_relaxed32(srcb2 + tid + 1024);
            unsigned w0, w1;
            for (;;) {
                if (((a0 >> 24) == exp8) && ((a1 >> 24) == exp8)) { w0 = a0; w1 = a1; break; }
                a0 = ld_relaxed32(srcb + tid);
                a1 = ld_relaxed32(srcb + tid + 1024);
                if (((b0 >> 24) == exp8) && ((b1 >> 24) == exp8)) { w0 = b0; w1 = b1; break; }
                b0 = ld_relaxed32(srcb2 + tid);
                b1 = ld_relaxed32(srcb2 + tid + 1024);
            }
            a_sf[tid]        = __uint_as_float(w0 << 8);   // restore sign+exp+mant15
            a_sf[tid + 1024] = __uint_as_float(w1 << 8);
        }
        __syncthreads();                                 // bar A
        float4 a4 = (t > 0) ? *(const float4*)&a_sf[4 * slot]
                            : make_float4(0.f, 0.f, 0.f, 0.f);

        // ---- Phase B: recurrent matvec on register weights ----
        float v[8];
        #pragma unroll
        for (int i = 0; i < 8; i++)
            v[i] = fmaf(w4[i].x, a4.x,
                   fmaf(w4[i].y, a4.y,
                   fmaf(w4[i].z, a4.z, w4[i].w * a4.w)));

        // select-then-shuffle fold: 8 accumulators -> row sums in lanes 0..7
        #pragma unroll
        for (int k = 0; k < 4; k++) {
            float give = (lane & 1) ? v[2 * k] : v[2 * k + 1];
            float got  = __shfl_xor_sync(0xFFFFFFFFu, give, 1);
            v[k] = ((lane & 1) ? v[2 * k + 1] : v[2 * k]) + got;
        }
        #pragma unroll
        for (int k = 0; k < 2; k++) {
            float give = (lane & 2) ? v[2 * k] : v[2 * k + 1];
            float got  = __shfl_xor_sync(0xFFFFFFFFu, give, 2);
            v[k] = ((lane & 2) ? v[2 * k + 1] : v[2 * k]) + got;
        }
        float s;
        {
            float give = (lane & 4) ? v[0] : v[1];
            float got  = __shfl_xor_sync(0xFFFFFFFFu, give, 4);
            s = ((lane & 4) ? v[1] : v[0]) + got;
        }
        s += __shfl_xor_sync(0xFFFFFFFFu, s, 8);
        s += __shfl_xor_sync(0xFFFFFFFFu, s, 16);
        if (lane < 8) red_s[half * 8 + lane][warp & 15] = s;
        __syncthreads();                                 // bar B

        // ---- Phase C: final reduce + nonlinearity + publish (threads 0..15) ----
        if (tid < ROWS_CTA) {
            const int row = tid;
            float4 s0 = *(const float4*)&red_s[row][0];
            float4 s1 = *(const float4*)&red_s[row][4];
            float4 s2 = *(const float4*)&red_s[row][8];
            float4 s3 = *(const float4*)&red_s[row][12];
            float sx = ((s0.x + s1.x) + (s2.x + s3.x)) + ((s0.y + s1.y) + (s2.y + s3.y));
            float sy = ((s0.z + s1.z) + (s2.z + s3.z)) + ((s0.w + s1.w) + (s2.w + s3.w));
            float tot = sx + sy;

            const float nh = (1.0f - LEAK) * hid_s[row] + LEAK * (ipc + tot);
            const float na = fast_tanh(nh);
            hid_s[row] = nh;

            const int gr = r0 + row;
            // round fp32 to top-24 bits (nearest), pack with 8-bit tag
            unsigned bits = __float_as_uint(na);
            unsigned pk = ((bits + 0x80u) >> 8) & 0x00FFFFFFu;
            pk |= ((unsigned)(base + t + 1) & 0xFFu) << 24;
            st_relaxed32(&g_tag32[t & 1][gr], pk);       // one 64B coalesced publish

            out_act[(size_t)t * HID + gr] = na;
            out_hid[(size_t)t * HID + gr] = nh;

            // advance ip pipeline (slack: consumed 2 steps from issue)
            ipc = ipn;
            int tn = (t + 2 < T_STEPS) ? t + 2 : T_STEPS - 1;
            ipn = __ldcg(&g_ip[(size_t)tn * HID + gr]);
        }
        // No trailing barrier: a_sf/red_s overwrites for step t+1 are gated by
        // bar A / bar B of t+1, which Phase C threads reach only after their
        // step-t reads are value-bound. g_tag32 slot overwrite (tag t+3, step
        // t+2) requires the producer's detect(t+2) <= all publishes(t+1) <= all
        // consumers' tag-(t+1) polls done — no reader is lapped; concurrent
        // writers differ by +-2 mod 256, never a false match.
    }

    if (tid == 0) g_base[cta][0] = base + T_STEPS;   // advance tags for next replay
}

extern "C" void kernel_launch(void* const* d_in, const int* in_sizes, int n_in,
                              void* d_out, int out_size) {
    const float* input = (const float*)d_in[0];   // [4096, 128]
    const float* w_ih  = (const float*)d_in[1];   // [2048, 128]
    const float* b_ih  = (const float*)d_in[2];   // [2048]
    const float* w_hh  = (const float*)d_in[3];   // [2048, 2048]
    float* out = (float*)d_out;                   // [2, 4096, 2048]

    reservoir_kernel<<<NCTA, NTHREADS>>>(input, w_ih, b_ih, w_hh, out);
}

// round 16
// speedup vs baseline: 2.9811x; 1.0956x over previous
#include <cuda_runtime.h>
#include <cstdint>

#define T_STEPS   4096
#define HID       2048
#define IN_DIM    128
#define NCTA      128
#define ROWS_CTA  16
#define NTHREADS  1024
#define LEAK      0.9f
#define TT        64      // prologue time-tile

typedef unsigned long long u64;

// Persistent cross-replay state. Tags are MONOTONIC mod 256 (base advances by
// T_STEPS per launch). Lockstep skew <= 1 step => live tags differ from the
// expected one by {0, +-2} mod 256 — exact-match is unambiguous.
__device__ unsigned g_tag32[2][HID];        // (tag8<<24) | (fp32 act rounded to top 24 bits)
__device__ int      g_base[NCTA][32];       // per-CTA base counter, 128B sector each
__device__ float    g_ip[T_STEPS * HID];    // precomputed input projection (32 MB, static)

__device__ __forceinline__ u64 ld_relaxed64(const u64* p) {
    u64 v;
    asm volatile("ld.relaxed.gpu.global.b64 %0, [%1];" : "=l"(v) : "l"(p));
    return v;
}
__device__ __forceinline__ void st_relaxed32(unsigned* p, unsigned v) {
    asm volatile("st.relaxed.gpu.global.b32 [%0], %1;" :: "l"(p), "r"(v));
}
// tanh(x) = sign(x) * (1 - 2/(exp(2|x|)+1)); MUFU-based.
__device__ __forceinline__ float fast_tanh(float x) {
    float e = __expf(2.0f * fabsf(x));
    float r = 1.0f - __fdividef(2.0f, e + 1.0f);
    return copysignf(r, x);
}

__global__ void __launch_bounds__(NTHREADS, 1)
reservoir_kernel(const float* __restrict__ input,   // [T, IN_DIM]
                 const float* __restrict__ w_ih,    // [HID, IN_DIM]
                 const float* __restrict__ b_ih,    // [HID]
                 const float* __restrict__ w_hh,    // [HID, HID]
                 float* __restrict__ out)           // [2, T, HID] (act, hid)
{
    // 33 KB pool: prologue overlays the input tile on top of main-loop a_sf/red_s
    __shared__ __align__(16) float shpool[TT * 132];          // 33792 B
    __shared__ __align__(16) float w_ih_s[ROWS_CTA][132];     // padded rows
    __shared__ float hid_s[ROWS_CTA];
    __shared__ float b_s[ROWS_CTA];
    __shared__ int   base_s;

    float*        a_sf  = shpool;                              // [2048] act broadcast
    float (*red_s)[16]  = (float(*)[16])(shpool + 2048);       // [16][16]
    float (*tile)[132]  = (float(*)[132])shpool;               // prologue overlay

    const int tid  = threadIdx.x;
    const int cta  = blockIdx.x;
    const int r0   = cta * ROWS_CTA;
    const int half = tid >> 9;       // 0: local rows 0..7, 1: rows 8..15
    const int slot = tid & 511;      // cols [4*slot, 4*slot+4)
    const int warp = tid >> 5;
    const int lane = tid & 31;

    // ---- one-time setup ----
    {
        const float4* w4p = (const float4*)(w_ih + r0 * IN_DIM);
        for (int i = tid; i < ROWS_CTA * (IN_DIM / 4); i += NTHREADS) {
            int row = i >> 5, c = i & 31;
            *(float4*)&w_ih_s[row][4 * c] = w4p[i];
        }
    }
    if (tid < ROWS_CTA) { b_s[tid] = b_ih[r0 + tid]; hid_s[tid] = 0.0f; }
    if (tid == 0) base_s = g_base[cta][0];

    // w_hh rows for this CTA -> registers (128 KB/CTA)
    float4 w4[8];
    {
        const float4* w_hh4 = (const float4*)w_hh;
        const int rbase = r0 + half * 8;
        #pragma unroll
        for (int i = 0; i < 8; i++)
            w4[i] = w_hh4[(size_t)(rbase + i) * (HID / 4) + slot];
    }

    // ---- PROLOGUE: inp_proj for this CTA's 16 rows, all T steps -> g_ip ----
    {
        const int trow = tid >> 4;          // 0..63
        const int row  = tid & 15;
        for (int t0 = 0; t0 < T_STEPS; t0 += TT) {
            __syncthreads();
            const float4* in4 = (const float4*)(input + t0 * IN_DIM);
            for (int i = tid; i < TT * (IN_DIM / 4); i += NTHREADS) {
                int tt = i >> 5, c = i & 31;
                *(float4*)&tile[tt][4 * c] = in4[i];
            }
            __syncthreads();
            float acc = 0.0f;
            #pragma unroll
            for (int j = 0; j < 32; j++) {
                float4 uv = *(const float4*)&tile[trow][4 * j];
                float4 wv = *(const float4*)&w_ih_s[row][4 * j];
                acc = fmaf(uv.x, wv.x, fmaf(uv.y, wv.y,
                      fmaf(uv.z, wv.z, fmaf(uv.w, wv.w, acc))));
            }
            g_ip[(size_t)(t0 + trow) * HID + r0 + row] = acc + b_s[row];
        }
    }
    __syncthreads();    // g_ip slice visible; tile overlay free for a_sf
    const int base = base_s;

    float* __restrict__ out_act = out;
    float* __restrict__ out_hid = out + (size_t)T_STEPS * HID;

    // ip register pipeline for Phase C threads (consume t, hold t+1, fetch t+2)
    float ipc = 0.0f, ipn = 0.0f;
    if (tid < ROWS_CTA) {
        ipc = __ldcg(&g_ip[(size_t)0 * HID + r0 + tid]);
        ipn = __ldcg(&g_ip[(size_t)1 * HID + r0 + tid]);
    }

    for (int t = 0; t < T_STEPS; t++) {
        // ---- Poll step t-1: ONE scalar b64 load covers this thread's 2 words
        // ({2tid, 2tid+1}, contiguous). Warp footprint: 256B = 2 sectors/iter
        // (proven-optimal); single scoreboard wait + one 64-bit masked tag
        // compare per iteration. Tag8 exact-match unambiguous (<=1-step skew).
        if (t > 0) {
            const unsigned exp8 = (unsigned)(base + t) & 0xFFu;
            const u64 pat  = ((u64)exp8 << 24) | ((u64)exp8 << 56);
            const u64 msk  = 0xFF000000FF000000ull;
            const u64* src = (const u64*)&g_tag32[(t - 1) & 1][0] + tid;
            u64 w;
            for (;;) {
                w = ld_relaxed64(src);
                if (((w ^ pat) & msk) == 0ull) break;
            }
            a_sf[2 * tid]     = __uint_as_float(((unsigned)w) << 8);        // restore top-24
            a_sf[2 * tid + 1] = __uint_as_float(((unsigned)(w >> 32)) << 8);
        }
        __syncthreads();                                 // bar A
        float4 a4 = (t > 0) ? *(const float4*)&a_sf[4 * slot]
                            : make_float4(0.f, 0.f, 0.f, 0.f);

        // ---- Phase B: recurrent matvec on register weights ----
        float v[8];
        #pragma unroll
        for (int i = 0; i < 8; i++)
            v[i] = fmaf(w4[i].x, a4.x,
                   fmaf(w4[i].y, a4.y,
                   fmaf(w4[i].z, a4.z, w4[i].w * a4.w)));

        // select-then-shuffle fold: 8 accumulators -> row sums in lanes 0..7
        #pragma unroll
        for (int k = 0; k < 4; k++) {
            float give = (lane & 1) ? v[2 * k] : v[2 * k + 1];
            float got  = __shfl_xor_sync(0xFFFFFFFFu, give, 1);
            v[k] = ((lane & 1) ? v[2 * k + 1] : v[2 * k]) + got;
        }
        #pragma unroll
        for (int k = 0; k < 2; k++) {
            float give = (lane & 2) ? v[2 * k] : v[2 * k + 1];
            float got  = __shfl_xor_sync(0xFFFFFFFFu, give, 2);
            v[k] = ((lane & 2) ? v[2 * k + 1] : v[2 * k]) + got;
        }
        float s;
        {
            float give = (lane & 4) ? v[0] : v[1];
            float got  = __shfl_xor_sync(0xFFFFFFFFu, give, 4);
            s = ((lane & 4) ? v[1] : v[0]) + got;
        }
        s += __shfl_xor_sync(0xFFFFFFFFu, s, 8);
        s += __shfl_xor_sync(0xFFFFFFFFu, s, 16);
        if (lane < 8) red_s[half * 8 + lane][warp & 15] = s;
        __syncthreads();                                 // bar B

        // ---- Phase C: final reduce + nonlinearity + publish (threads 0..15) ----
        if (tid < ROWS_CTA) {
            const int row = tid;
            float4 s0 = *(const float4*)&red_s[row][0];
            float4 s1 = *(const float4*)&red_s[row][4];
            float4 s2 = *(const float4*)&red_s[row][8];
            float4 s3 = *(const float4*)&red_s[row][12];
            float sx = ((s0.x + s1.x) + (s2.x + s3.x)) + ((s0.y + s1.y) + (s2.y + s3.y));
            float sy = ((s0.z + s1.z) + (s2.z + s3.z)) + ((s0.w + s1.w) + (s2.w + s3.w));
            float tot = sx + sy;

            const float nh = (1.0f - LEAK) * hid_s[row] + LEAK * (ipc + tot);
            const float na = fast_tanh(nh);
            hid_s[row] = nh;

            const int gr = r0 + row;
            // round fp32 to top-24 bits (nearest), pack with 8-bit tag
            unsigned bits = __float_as_uint(na);
            unsigned pk = ((bits + 0x80u) >> 8) & 0x00FFFFFFu;
            pk |= ((unsigned)(base + t + 1) & 0xFFu) << 24;
            st_relaxed32(&g_tag32[t & 1][gr], pk);       // one 64B coalesced publish

            out_act[(size_t)t * HID + gr] = na;
            out_hid[(size_t)t * HID + gr] = nh;

            // advance ip pipeline (slack: consumed 2 steps from issue)
            ipc = ipn;
            int tn = (t + 2 < T_STEPS) ? t + 2 : T_STEPS - 1;
            ipn = __ldcg(&g_ip[(size_t)tn * HID + gr]);
        }
        // No trailing barrier: a_sf/red_s overwrites for step t+1 are gated by
        // bar A / bar B of t+1, which Phase C threads reach only after their
        // step-t reads are value-bound. g_tag32 slot overwrite (tag t+3, step
        // t+2) requires the producer's detect(t+2) <= all publishes(t+1) <= all
        // consumers' tag-(t+1) polls done — no reader is lapped; concurrent
        // writers differ by +-2 mod 256, never a false match.
    }

    if (tid == 0) g_base[cta][0] = base + T_STEPS;   // advance tags for next replay
}

extern "C" void kernel_launch(void* const* d_in, const int* in_sizes, int n_in,
                              void* d_out, int out_size) {
    const float* input = (const float*)d_in[0];   // [4096, 128]
    const float* w_ih  = (const float*)d_in[1];   // [2048, 128]
    const float* b_ih  = (const float*)d_in[2];   // [2048]
    const float* w_hh  = (const float*)d_in[3];   // [2048, 2048]
    float* out = (float*)d_out;                   // [2, 4096, 2048]

    reservoir_kernel<<<NCTA, NTHREADS>>>(input, w_ih, b_ih, w_hh, out);
}